// round 17
// baseline (speedup 1.0000x reference)
#include <cuda_runtime.h>

#define BATCH   64
#define NTOK    4096
#define CH      1024
#define KANCH   8
#define NSPLIT  16
#define TOK_PER (NTOK / NSPLIT)   // 256
#define C4      (CH / 4)          // 256 float4 per row

// Scratch (device globals — no allocation allowed).
// __align__(16): accessed through float4* (R11/R12 trapped without it).
__device__ __align__(16) float g_partial[NSPLIT * BATCH * CH];  // 4 MB
__device__ __align__(16) float g_desc[BATCH * CH];              // normalized descriptors
__device__ int      g_ids[BATCH];
__device__ unsigned g_cnt[BATCH];   // per-batch arrival counters
// Counters are monotone: (old % 16 == 15) detects the last arrival of THIS
// replay, so no reset is needed and the kernels stay graph-replayable.

// ---------------------------------------------------------------------------
// Fused kernel: streaming partial sums (HBM-bound, 1 GiB) + per-batch
// combiner. The 16th block to finish a batch combines its partials, computes
// the normalized descriptor, cosine sims and argmax — overlapped with the
// rest of the streaming work. ~145-158us at ~86% DRAM (practical ceiling).
// ---------------------------------------------------------------------------
__global__ __launch_bounds__(256, 8) void k_main(const float* __restrict__ x,
                                                 const float* __restrict__ anchors,
                                                 float* __restrict__ out) {
    const int ns = blockIdx.x;
    const int b  = blockIdx.y;
    const int t  = threadIdx.x;  // 0..255 -> channels 4t..4t+3

    // ---- streaming phase (__ldcs: read-once data, evict-first) ----
    {
        const float4* p = reinterpret_cast<const float4*>(x)
                        + (size_t)b * NTOK * C4
                        + (size_t)ns * TOK_PER * C4
                        + t;
        float4 acc = make_float4(0.f, 0.f, 0.f, 0.f);
#pragma unroll 8
        for (int n = 0; n < TOK_PER; ++n) {
            float4 v = __ldcs(p);
            p += C4;
            acc.x += v.x; acc.y += v.y; acc.z += v.z; acc.w += v.w;
        }
        reinterpret_cast<float4*>(g_partial)[(size_t)(ns * BATCH + b) * C4 + t] = acc;
    }

    __threadfence();
    __syncthreads();
    __shared__ unsigned s_old;
    if (t == 0) s_old = atomicAdd(&g_cnt[b], 1u);
    __syncthreads();
    if ((s_old & 15u) != 15u) return;   // not the last arrival for this batch

    __threadfence();   // acquire: order peers' partial stores before our loads

    // ---- combiner phase (one block per batch, 63/64 overlapped) ----
    const int lane = t & 31;
    const int w    = t >> 5;

    float4 s = make_float4(0.f, 0.f, 0.f, 0.f);
#pragma unroll
    for (int nsi = 0; nsi < NSPLIT; ++nsi) {
        float4 v = __ldcg(reinterpret_cast<const float4*>(g_partial)
                          + (size_t)(nsi * BATCH + b) * C4 + t);
        s.x += v.x; s.y += v.y; s.z += v.z; s.w += v.w;
    }
    const float inv_n = 1.0f / (float)NTOK;
    s.x *= inv_n; s.y *= inv_n; s.z *= inv_n; s.w *= inv_n;

    __shared__ float warp_s[8];
    __shared__ float s_invnorm;
    float ss = s.x * s.x + s.y * s.y + s.z * s.z + s.w * s.w;
#pragma unroll
    for (int off = 16; off > 0; off >>= 1)
        ss += __shfl_xor_sync(0xffffffffu, ss, off);
    if (lane == 0) warp_s[w] = ss;
    __syncthreads();
    if (t == 0) {
        float tot = 0.f;
#pragma unroll
        for (int i = 0; i < 8; ++i) tot += warp_s[i];
        s_invnorm = 1.0f / fmaxf(sqrtf(tot), 1e-12f);
    }
    __syncthreads();

    const float invn = s_invnorm;
    float4 d = make_float4(s.x * invn, s.y * invn, s.z * invn, s.w * invn);
    reinterpret_cast<float4*>(g_desc)[(size_t)b * C4 + t] = d;

    float dot[KANCH];
#pragma unroll
    for (int k = 0; k < KANCH; ++k) {
        float4 a = __ldg(reinterpret_cast<const float4*>(anchors) + (size_t)k * C4 + t);
        dot[k] = d.x * a.x + d.y * a.y + d.z * a.z + d.w * a.w;
    }
#pragma unroll
    for (int off = 16; off > 0; off >>= 1) {
#pragma unroll
        for (int k = 0; k < KANCH; ++k)
            dot[k] += __shfl_xor_sync(0xffffffffu, dot[k], off);
    }
    __shared__ float wd[8][KANCH];
    if (lane == 0) {
#pragma unroll
        for (int k = 0; k < KANCH; ++k) wd[w][k] = dot[k];
    }
    __syncthreads();
    if (t == 0) {
        float simk[KANCH];
#pragma unroll
        for (int k = 0; k < KANCH; ++k) {
            float acc = 0.f;
#pragma unroll
            for (int i = 0; i < 8; ++i) acc += wd[i][k];
            simk[k] = acc;
        }
        // argmin(1 - sim) == first max of sim (strict > keeps first occurrence)
        int   best   = 0;
        float best_s = simk[0];
#pragma unroll
        for (int k = 1; k < KANCH; ++k)
            if (simk[k] > best_s) { best_s = simk[k]; best = k; }
        g_ids[b] = best;
        out[b]   = (float)best;
    }
}

// ---------------------------------------------------------------------------
// k_ema5: 4-warps-per-anchor EMA (8 independent chains; in-chain batch order
// preserved => equivalent to the sequential scan).
// R16 post-mortem: the 12us plateau (R15=R16 despite halved loads) points at
// per-step DRAM misses (ncu flushes L2; timed-run residency uncertain after
// k_main streams 1 GB) plus a serial list-build.
// R17: (1) prefetch.global.L2 warm sweep over g_desc/anchors/ids/counts at
// entry — per-step chain loads become L2 hits hidden under the reduce;
// (2) ballot-based list build (no serial scan, no s_list smem).
// Scalar-scale trick kept: a_true = scale*raw; |v|^2 in [0.64,1.21].
// ---------------------------------------------------------------------------
__global__ __launch_bounds__(1024) void k_ema5(const float* __restrict__ anchors,
                                               const float* __restrict__ counts,
                                               float* __restrict__ out) {
    __shared__ float wpart[2][KANCH][4];   // [parity][anchor][quarter]

    const int t    = threadIdx.x;   // 0..1023
    const int lane = t & 31;
    const int q    = (t >> 5) & 3;  // quarter of the anchor, 0..3
    const int g    = t >> 7;        // anchor id, 0..7

    // ---- L2 warm: fire-and-forget prefetch of everything the chains read ----
    {
        const char* db = reinterpret_cast<const char*>(g_desc);
        // 64*1024*4 B = 256 KB = 2048 x 128B lines -> 2 per thread
#pragma unroll
        for (int i = 0; i < 2; ++i)
            asm volatile("prefetch.global.L2 [%0];"
                         :: "l"(db + (size_t)(t + i * 1024) * 128));
        if (t < 256)   // anchors: 32 KB = 256 lines
            asm volatile("prefetch.global.L2 [%0];"
                         :: "l"(reinterpret_cast<const char*>(anchors) + (size_t)t * 128));
        if (t == 0) {
            asm volatile("prefetch.global.L2 [%0];" :: "l"(g_ids));
            asm volatile("prefetch.global.L2 [%0];" :: "l"(counts));
        }
    }

    // ---- ballot list build: 64-bit membership mask per anchor ----
    const int id0 = g_ids[lane];
    const int id1 = g_ids[32 + lane];
    const unsigned m0 = __ballot_sync(0xffffffffu, id0 == g);
    const unsigned m1 = __ballot_sync(0xffffffffu, id1 == g);
    const unsigned long long mm =
        ((unsigned long long)m1 << 32) | (unsigned long long)m0;
    const int len = __popcll(mm);

    // Lane l caches chain entries l and 32+l (batch order = ascending bits).
    int myl0, myl1;
    {
        unsigned long long a = mm;
        for (int k = 0; k < lane; ++k) a &= a - 1;          // clear low bits
        myl0 = __ffsll((long long)a) - 1;                   // -1 if none
        unsigned long long b2 = mm;
        for (int k = 0; k < 32 + lane; ++k) b2 &= b2 - 1;
        myl1 = __ffsll((long long)b2) - 1;
    }

    // Thread owns C4-indices {j*128 + q*32 + lane : j in 0..1} of anchor g.
    const int base = q * 32 + lane;
    float4 A[2];
#pragma unroll
    for (int j = 0; j < 2; ++j)
        A[j] = __ldg(reinterpret_cast<const float4*>(anchors)
                     + (size_t)g * C4 + j * 128 + base);
    float c     = __ldg(counts + g);
    float scale = 1.0f;             // a_true = scale * A

    // Prefetch first sample's slice (2 batched LDG.128).
    float4 d[2];
    if (len > 0) {
        const int b0 = __shfl_sync(0xffffffffu, myl0, 0);
#pragma unroll
        for (int j = 0; j < 2; ++j)
            d[j] = __ldg(reinterpret_cast<const float4*>(g_desc)
                         + (size_t)b0 * C4 + j * 128 + base);
    }

    for (int i = 0; i < len; ++i) {
        const float m  = (c < 1.0f) ? 0.0f : 0.9f;
        const float im = 1.0f - m;
        const float ma = m * scale;

        float s0 = 0.f, s1 = 0.f;
#pragma unroll
        for (int j = 0; j < 2; ++j) {
            A[j].x = ma * A[j].x + im * d[j].x;
            A[j].y = ma * A[j].y + im * d[j].y;
            A[j].z = ma * A[j].z + im * d[j].z;
            A[j].w = ma * A[j].w + im * d[j].w;
            s0 += A[j].x * A[j].x + A[j].z * A[j].z;
            s1 += A[j].y * A[j].y + A[j].w * A[j].w;
        }

        // Prefetch next sample's slice; overlaps the reduce + barrier below.
        if (i + 1 < len) {
            const int nxt = i + 1;
            const int bn  = __shfl_sync(0xffffffffu,
                                        (nxt < 32) ? myl0 : myl1, nxt & 31);
#pragma unroll
            for (int j = 0; j < 2; ++j)
                d[j] = __ldg(reinterpret_cast<const float4*>(g_desc)
                             + (size_t)bn * C4 + j * 128 + base);
        }

        float ssum = s0 + s1;
#pragma unroll
        for (int off = 16; off > 0; off >>= 1)
            ssum += __shfl_xor_sync(0xffffffffu, ssum, off);
        if (lane == 0) wpart[i & 1][g][q] = ssum;

        asm volatile("bar.sync %0, 128;" :: "r"(g + 1) : "memory");

        const float tot = (wpart[i & 1][g][0] + wpart[i & 1][g][1])
                        + (wpart[i & 1][g][2] + wpart[i & 1][g][3]);
        scale = rsqrtf(tot);        // |v| in [0.8, 1.1]; eps guard never binds
        c += 1.0f;
        // wpart slot (i&1) is rewritten at step i+2, after the barrier of
        // step i+1 -> no WAR hazard.
    }

    // Emit new_anchors (scale applied) then new_counts.
#pragma unroll
    for (int j = 0; j < 2; ++j) {
        float4 v = A[j];
        v.x *= scale; v.y *= scale; v.z *= scale; v.w *= scale;
        reinterpret_cast<float4*>(out + BATCH)[(size_t)g * C4 + j * 128 + base] = v;
    }
    if ((t & 127) == 0) out[BATCH + KANCH * CH + g] = c;
}

// ---------------------------------------------------------------------------
extern "C" void kernel_launch(void* const* d_in, const int* in_sizes, int n_in,
                              void* d_out, int out_size) {
    const float* prompt_tokens = (const float*)d_in[0];  // [64,4096,1024] f32
    const float* anchors       = (const float*)d_in[1];  // [8,1024] f32
    const float* counts        = (const float*)d_in[2];  // [8] f32
    float* out = (float*)d_out;  // [64 ids | 8192 anchors | 8 counts] f32

    dim3 grid1(NSPLIT, BATCH);
    k_main<<<grid1, 256>>>(prompt_tokens, anchors, out);
    k_ema5<<<1, 1024>>>(anchors, counts, out);
}